// round 13
// baseline (speedup 1.0000x reference)
#include <cuda_runtime.h>
#include <cstdint>

#define H 256
#define DD 64

// ---------------- persistent device state (no allocations) ----------------
__device__ __align__(16) float g_G[H * H];          // Gram (symmetric)
__device__ __align__(16) float g_h1[H], g_h2[H], g_u3[H];   // h', h'', h'''*s
__device__ __align__(16) float g_L[H], g_Y[H];      // L[n], Y[n]
__device__ __align__(16) float g_gd[4][H];          // g'..g'''' at a_n
__device__ __align__(16) float4 g_part[8][H];       // per-tile-col {Q,R,Z,U} partials
__device__ unsigned int g_done = 0;

// ---------------- kernel 1: Gram (blocks 0-127) + chains/L/Y/g-chain (block 128) ----
__global__ __launch_bounds__(256) void k_pre(
    const float* __restrict__ x,  const float* __restrict__ W1,
    const float* __restrict__ b1, const float* __restrict__ W2,
    const float* __restrict__ b2)
{
    int tid = threadIdx.x;
    if (blockIdx.x < 128) {
        __shared__ float srow[2][DD];
        int m0 = 2 * blockIdx.x;
        if (tid < 2 * DD) srow[tid >> 6][tid & 63] = W1[(m0 + (tid >> 6)) * DD + (tid & 63)];
        __syncthreads();
        const float4* myr = (const float4*)(W1 + tid * DD);
        float a0 = 0.f, a1 = 0.f;
#pragma unroll
        for (int i = 0; i < DD / 4; i++) {
            float4 v = __ldg(myr + i);
            a0 += srow[0][4*i]*v.x + srow[0][4*i+1]*v.y + srow[0][4*i+2]*v.z + srow[0][4*i+3]*v.w;
            a1 += srow[1][4*i]*v.x + srow[1][4*i+1]*v.y + srow[1][4*i+2]*v.z + srow[1][4*i+3]*v.w;
        }
        g_G[(m0 + 0) * H + tid] = a0;
        g_G[(m0 + 1) * H + tid] = a1;
    } else {
        __shared__ float sx[DD];
        __shared__ float sh[H], sh2s[H], sh4s2[H];
        if (tid < DD) sx[tid] = x[tid];
        __syncthreads();

        int m = tid;
        float z = b1[m], s = 0.f;
        const float4* wr = (const float4*)(W1 + m * DD);
#pragma unroll
        for (int i = 0; i < DD / 4; i++) {
            float4 w = __ldg(wr + i);
            float4 xv = *(const float4*)(sx + 4 * i);
            z += w.x * xv.x + w.y * xv.y + w.z * xv.z + w.w * xv.w;
            s += w.x * w.x + w.y * w.y + w.z * w.z + w.w * w.w;
        }
        float h = tanhf(z), w = 1.f - h * h;
        float h2 = -2.f * h * w;
        float h3 = (4.f * h * h - 2.f * w) * w;
        float h4 = (16.f * w - 8.f * h * h) * h * w;
        g_h1[m] = w;
        g_h2[m] = h2;
        g_u3[m] = h3 * s;
        sh[m] = h;
        sh2s[m] = h2 * s;
        sh4s2[m] = h4 * s * s;
        __syncthreads();

        // per-n: a_n, L[n], Y[n] from one W2-row pass; then g-chain
        int n = tid;
        float a = b2[n], L = 0.f, Y = 0.f;
        const float4* w2r = (const float4*)(W2 + n * H);
#pragma unroll 8
        for (int i = 0; i < H / 4; i++) {
            float4 wv = __ldg(w2r + i);
            a += wv.x * sh[4*i]    + wv.y * sh[4*i+1]    + wv.z * sh[4*i+2]    + wv.w * sh[4*i+3];
            L += wv.x * sh2s[4*i]  + wv.y * sh2s[4*i+1]  + wv.z * sh2s[4*i+2]  + wv.w * sh2s[4*i+3];
            Y += wv.x * sh4s2[4*i] + wv.y * sh4s2[4*i+1] + wv.z * sh4s2[4*i+2] + wv.w * sh4s2[4*i+3];
        }
        g_L[n] = L;
        g_Y[n] = Y;
        float g = tanhf(a), gw = 1.f - g * g;
        g_gd[0][n] = gw;
        g_gd[1][n] = -2.f * g * gw;
        g_gd[2][n] = (4.f * g * g - 2.f * gw) * gw;
        g_gd[3][n] = (16.f * gw - 8.f * g * g) * g * gw;
    }
}

// ---------------- kernel 2: tiled GEMM (M, P) + contraction epilogue ----------------
// Block (i,j): 32n x 32t tile, K=256 fully staged in smem.
//   M[n,t] = sum_k (W2[n,k] h1[k]) G[k,t];  P[n,t] = sum_k (W2[n,k] h2[k]) G[k,t]^2
// Epilogue: partial Q,R,Z,U over tile's t-columns -> g_part[j][n].
// Last-ticket block: combine 8 partials + L,Y + g-chain + W3 dot -> out.
__global__ __launch_bounds__(256) void k_gemm(
    const float* __restrict__ W2, const float* __restrict__ W3,
    float* __restrict__ out)
{
    extern __shared__ float4 smem4[];
    float4* sA  = smem4;           // 32 x 65 float4 (stride-pad: conflict-free)
    float4* sB  = smem4 + 2080;
    float4* sGT = smem4 + 4160;    // G rows t0..t0+31 (symmetry: = columns)

    int tid = threadIdx.x;
    int bi = blockIdx.x >> 3, bj = blockIdx.x & 7;
    int n0 = bi * 32, t0 = bj * 32;

    // ---- staging: 8 float4 per thread per array ----
    const float4* W2v = (const float4*)W2;
    const float4* Gv  = (const float4*)g_G;
    const float4* h1v = (const float4*)g_h1;
    const float4* h2v = (const float4*)g_h2;
#pragma unroll
    for (int u = 0; u < 8; u++) {
        int idx = u * 256 + tid;
        int row = idx >> 6, col = idx & 63;
        float4 w = __ldg(W2v + (n0 + row) * 64 + col);
        float4 c1 = __ldg(h1v + col);
        float4 c2 = __ldg(h2v + col);
        sA[row * 65 + col] = make_float4(w.x*c1.x, w.y*c1.y, w.z*c1.z, w.w*c1.w);
        sB[row * 65 + col] = make_float4(w.x*c2.x, w.y*c2.y, w.z*c2.z, w.w*c2.w);
        sGT[row * 65 + col] = __ldg(Gv + (t0 + row) * 64 + col);
    }
    __syncthreads();

    // ---- main loop: micro-tile 2 rows x 2 cols per thread ----
    int ty = tid >> 4, tx = tid & 15;
    int r0 = 2 * ty, r1 = r0 + 1;
    const float4* pa0 = sA + r0 * 65;
    const float4* pa1 = sA + r1 * 65;
    const float4* pb0 = sB + r0 * 65;
    const float4* pb1 = sB + r1 * 65;
    const float4* pg0 = sGT + tx * 65;
    const float4* pg1 = sGT + (tx + 16) * 65;

    float M00 = 0.f, M01 = 0.f, M10 = 0.f, M11 = 0.f;
    float P00 = 0.f, P01 = 0.f, P10 = 0.f, P11 = 0.f;
#pragma unroll 4
    for (int kk = 0; kk < 64; kk++) {
        float4 a0 = pa0[kk], a1 = pa1[kk];
        float4 b0 = pb0[kk], b1 = pb1[kk];
        float4 g0 = pg0[kk], g1 = pg1[kk];
        M00 += a0.x*g0.x + a0.y*g0.y + a0.z*g0.z + a0.w*g0.w;
        M01 += a0.x*g1.x + a0.y*g1.y + a0.z*g1.z + a0.w*g1.w;
        M10 += a1.x*g0.x + a1.y*g0.y + a1.z*g0.z + a1.w*g0.w;
        M11 += a1.x*g1.x + a1.y*g1.y + a1.z*g1.z + a1.w*g1.w;
        float4 q0 = make_float4(g0.x*g0.x, g0.y*g0.y, g0.z*g0.z, g0.w*g0.w);
        float4 q1 = make_float4(g1.x*g1.x, g1.y*g1.y, g1.z*g1.z, g1.w*g1.w);
        P00 += b0.x*q0.x + b0.y*q0.y + b0.z*q0.z + b0.w*q0.w;
        P01 += b0.x*q1.x + b0.y*q1.y + b0.z*q1.z + b0.w*q1.w;
        P10 += b1.x*q0.x + b1.y*q0.y + b1.z*q0.z + b1.w*q0.w;
        P11 += b1.x*q1.x + b1.y*q1.y + b1.z*q1.z + b1.w*q1.w;
    }

    // ---- epilogue: partial contractions over this tile's 32 t-columns ----
    int gn0 = n0 + r0, gn1 = n0 + r1;
    int gc0 = t0 + tx, gc1 = t0 + tx + 16;
    float h1c0 = g_h1[gc0], h1c1 = g_h1[gc1];
    float h2c0 = g_h2[gc0], h2c1 = g_h2[gc1];
    float u3c0 = g_u3[gc0], u3c1 = g_u3[gc1];
    float w00 = __ldg(&W2[gn0 * H + gc0]), w01 = __ldg(&W2[gn0 * H + gc1]);
    float w10 = __ldg(&W2[gn1 * H + gc0]), w11 = __ldg(&W2[gn1 * H + gc1]);

    float q0 = w00*h1c0*M00 + w01*h1c1*M01;
    float r0v = w00*h2c0*M00*M00 + w01*h2c1*M01*M01;
    float z0 = w00*h2c0*P00 + w01*h2c1*P01;
    float u0 = w00*u3c0*M00 + w01*u3c1*M01;
    float q1 = w10*h1c0*M10 + w11*h1c1*M11;
    float r1v = w10*h2c0*M10*M10 + w11*h2c1*M11*M11;
    float z1 = w10*h2c0*P10 + w11*h2c1*P11;
    float u1 = w10*u3c0*M10 + w11*u3c1*M11;

#pragma unroll
    for (int off = 8; off > 0; off >>= 1) {
        q0  += __shfl_down_sync(0xFFFFFFFFu, q0,  off, 16);
        r0v += __shfl_down_sync(0xFFFFFFFFu, r0v, off, 16);
        z0  += __shfl_down_sync(0xFFFFFFFFu, z0,  off, 16);
        u0  += __shfl_down_sync(0xFFFFFFFFu, u0,  off, 16);
        q1  += __shfl_down_sync(0xFFFFFFFFu, q1,  off, 16);
        r1v += __shfl_down_sync(0xFFFFFFFFu, r1v, off, 16);
        z1  += __shfl_down_sync(0xFFFFFFFFu, z1,  off, 16);
        u1  += __shfl_down_sync(0xFFFFFFFFu, u1,  off, 16);
    }
    if (tx == 0) {
        g_part[bj][gn0] = make_float4(q0, r0v, z0, u0);
        g_part[bj][gn1] = make_float4(q1, r1v, z1, u1);
    }

    // ---- ticket: last block combines everything ----
    __threadfence();
    __shared__ unsigned int slast;
    __shared__ double sdr[8];
    if (tid == 0) slast = (atomicAdd(&g_done, 1u) == 63u) ? 1u : 0u;
    __syncthreads();
    if (slast) {
        __threadfence();
        int n = tid;
        float Q = 0.f, R = 0.f, Z = 0.f, U = 0.f;
#pragma unroll
        for (int j = 0; j < 8; j++) {
            float4 v = g_part[j][n];
            Q += v.x; R += v.y; Z += v.z; U += v.w;
        }
        float L = g_L[n], Y = g_Y[n];
        float g1 = g_gd[0][n], g2 = g_gd[1][n], g3 = g_gd[2][n], g4 = g_gd[3][n];
        float val = g4 * Q * Q
                  + g3 * (2.f * L * Q + 4.f * R)
                  + g2 * (L * L + 2.f * Z + 4.f * U)
                  + g1 * Y;
        double d = (double)(__ldg(&W3[n]) * val);
#pragma unroll
        for (int off = 16; off > 0; off >>= 1)
            d += __shfl_down_sync(0xFFFFFFFFu, d, off);
        int wid = tid >> 5, lane = tid & 31;
        if (lane == 0) sdr[wid] = d;
        __syncthreads();
        if (wid == 0) {
            double v = (lane < 8) ? sdr[lane] : 0.0;
#pragma unroll
            for (int off = 4; off > 0; off >>= 1)
                v += __shfl_down_sync(0xFFu, v, off);
            if (lane == 0) {
                out[0] = (float)v;
                g_done = 0u;      // reset for next graph replay
                __threadfence();
            }
        }
    }
}

// ---------------- launch ----------------
extern "C" void kernel_launch(void* const* d_in, const int* in_sizes, int n_in,
                              void* d_out, int out_size) {
    const float* x  = (const float*)d_in[0];
    const float* W1 = (const float*)d_in[1];
    const float* b1 = (const float*)d_in[2];
    const float* W2 = (const float*)d_in[3];
    const float* b2 = (const float*)d_in[4];
    const float* W3 = (const float*)d_in[5];
    // d_in[6] = b3: does not affect the 4th derivative
    float* out = (float*)d_out;

    const int smem = 6240 * 16;   // 3 x (32 x 65) float4 = 99840 B
    cudaFuncSetAttribute(k_gemm, cudaFuncAttributeMaxDynamicSharedMemorySize, smem);

    k_pre<<<129, 256>>>(x, W1, b1, W2, b2);
    k_gemm<<<64, 256, smem>>>(W2, W3, out);
}

// round 14
// speedup vs baseline: 1.7047x; 1.7047x over previous
#include <cuda_runtime.h>
#include <cstdint>

#define H 256
#define DD 64
#define NPAIR 128
#define NBM (2 * NPAIR)     // k_main blocks: (pair, t-half)

// ---------------- persistent device state (no allocations) ----------------
__device__ __align__(16) float g_G[H * H];          // Gram (symmetric)
__device__ __align__(16) float g_h[H], g_h1[H], g_h2[H], g_u3[H], g_h2s[H], g_h4s2[H];
__device__ __align__(16) float g_QRZU[NPAIR][8];    // zeroed by k_pre each replay
__device__ __align__(16) float g_aLY[NPAIR][6];     // {a0,L0,Y0,a1,L1,Y1} (full values)
__device__ unsigned int g_done = 0;

// ---------------- kernel 1: Gram (blocks 0-127, also zero partials) + chain (block 128) ----
__global__ __launch_bounds__(256) void k_pre(
    const float* __restrict__ x,  const float* __restrict__ W1,
    const float* __restrict__ b1)
{
    int tid = threadIdx.x;
    if (blockIdx.x < 128) {
        __shared__ float srow[2][DD];
        int m0 = 2 * blockIdx.x;
        if (tid < 2 * DD) srow[tid >> 6][tid & 63] = W1[(m0 + (tid >> 6)) * DD + (tid & 63)];
        if (tid < 8)  g_QRZU[blockIdx.x][tid] = 0.f;   // zero partial slab for this pair
        __syncthreads();
        const float4* myr = (const float4*)(W1 + tid * DD);
        float a0 = 0.f, a1 = 0.f;
#pragma unroll
        for (int i = 0; i < DD / 4; i++) {
            float4 v = __ldg(myr + i);
            a0 += srow[0][4*i]*v.x + srow[0][4*i+1]*v.y + srow[0][4*i+2]*v.z + srow[0][4*i+3]*v.w;
            a1 += srow[1][4*i]*v.x + srow[1][4*i+1]*v.y + srow[1][4*i+2]*v.z + srow[1][4*i+3]*v.w;
        }
        g_G[(m0 + 0) * H + tid] = a0;
        g_G[(m0 + 1) * H + tid] = a1;
    } else {
        // layer-1 chain vectors only (no GEMV here -- that was the straggler)
        __shared__ float sx[DD];
        if (tid < DD) sx[tid] = x[tid];
        __syncthreads();
        int m = tid;
        float z = b1[m], s = 0.f;
        const float4* wr = (const float4*)(W1 + m * DD);
#pragma unroll
        for (int i = 0; i < DD / 4; i++) {
            float4 w = __ldg(wr + i);
            float4 xv = *(const float4*)(sx + 4 * i);
            z += w.x * xv.x + w.y * xv.y + w.z * xv.z + w.w * xv.w;
            s += w.x * w.x + w.y * w.y + w.z * w.z + w.w * w.w;
        }
        float h = tanhf(z), w = 1.f - h * h;
        float h2 = -2.f * h * w;
        float h3 = (4.f * h * h - 2.f * w) * w;
        float h4 = (16.f * w - 8.f * h * h) * h * w;
        g_h[m]    = h;
        g_h1[m]   = w;
        g_h2[m]   = h2;
        g_u3[m]   = h3 * s;
        g_h2s[m]  = h2 * s;
        g_h4s2[m] = h4 * s * s;
    }
}

// ---------------- kernel 2: streaming contraction, grid = (pair, t-half) ----------------
__global__ __launch_bounds__(256, 2) void k_main(
    const float* __restrict__ W2, const float* __restrict__ W3,
    const float* __restrict__ b2, float* __restrict__ out)
{
    __shared__ float  sP[8 * 32 * 16];   // phase-1 partials [ms][ts][16] = 16KB
    __shared__ float4 sAB[H];            // {A0, A1, B0, B1} (4KB)
    __shared__ float  sU0[H], sU1[H];    // 2KB
    __shared__ float  sred[4][8];
    __shared__ float  sredA[8][6];
    __shared__ double sdr[8];

    int tid = threadIdx.x;
    int bx = blockIdx.x;
    int p = bx >> 1, hf = bx & 1;
    int wid = tid >> 5, lane = tid & 31;
    int n0 = 2 * p;

    // ---- setup: coefficient vectors + full-m a/L/Y partials ----
    float aa0, aa1, LL0, LL1, YY0, YY1;
    {
        int m = tid;
        float h1 = g_h1[m], h2 = g_h2[m], u3 = g_u3[m];
        float hh = g_h[m], h2s = g_h2s[m], h4s2 = g_h4s2[m];
        float w20 = __ldg(&W2[n0 * H + m]);
        float w21 = __ldg(&W2[(n0 + 1) * H + m]);
        sAB[m] = make_float4(w20 * h1, w21 * h1, w20 * h2, w21 * h2);
        sU0[m] = w20 * u3;
        sU1[m] = w21 * u3;
        aa0 = w20 * hh;   aa1 = w21 * hh;
        LL0 = w20 * h2s;  LL1 = w21 * h2s;
        YY0 = w20 * h4s2; YY1 = w21 * h4s2;
    }
    // hf=0 publishes full a/L/Y for this pair (block reduce over all 256 m)
    if (hf == 0) {
        float v[6] = {aa0, LL0, YY0, aa1, LL1, YY1};
#pragma unroll
        for (int k = 0; k < 6; k++) {
            float t = v[k];
#pragma unroll
            for (int o = 16; o > 0; o >>= 1) t += __shfl_down_sync(0xFFFFFFFFu, t, o);
            v[k] = t;
        }
        if (lane == 0) {
#pragma unroll
            for (int k = 0; k < 6; k++) sredA[wid][k] = v[k];
        }
    }
    __syncthreads();
    if (hf == 0 && tid < 6) {
        float t = 0.f;
#pragma unroll
        for (int w = 0; w < 8; w++) t += sredA[w][tid];
        g_aLY[p][tid == 0 ? 0 : (tid == 1 ? 1 : (tid == 2 ? 2 : tid))] = 0.f; // placeholder avoided below
    }
    // (simple direct form)
    if (hf == 0 && tid < 6) {
        float t = 0.f;
#pragma unroll
        for (int w = 0; w < 8; w++) t += sredA[w][tid];
        g_aLY[p][tid] = t;
    }

    // ---- phase 1: pipelined G stream; thread = (ms = tid>>5, ts = tid&31) ----
    int ms = tid >> 5, ts = tid & 31;
    float M0[4] = {0,0,0,0}, M1[4] = {0,0,0,0};
    float P0[4] = {0,0,0,0}, P1[4] = {0,0,0,0};

    const float4* Gp = (const float4*)g_G + (32 * ms) * (H / 4) + hf * 32 + ts;
    const float4* abp = sAB + 32 * ms;

    float4 buf[2][8];
#pragma unroll
    for (int u = 0; u < 8; u++) buf[0][u] = __ldg(Gp + u * (H / 4));

#pragma unroll
    for (int bb = 0; bb < 4; bb++) {
        int cur = bb & 1, nxt = cur ^ 1;
        if (bb < 3) {
#pragma unroll
            for (int u = 0; u < 8; u++)
                buf[nxt][u] = __ldg(Gp + (8 * (bb + 1) + u) * (H / 4));
        }
#pragma unroll
        for (int u = 0; u < 8; u++) {
            float4 ab = abp[8 * bb + u];
            float4 g = buf[cur][u];
            M0[0] += ab.x * g.x;  M0[1] += ab.x * g.y;  M0[2] += ab.x * g.z;  M0[3] += ab.x * g.w;
            M1[0] += ab.y * g.x;  M1[1] += ab.y * g.y;  M1[2] += ab.y * g.z;  M1[3] += ab.y * g.w;
            float gg0 = g.x * g.x, gg1 = g.y * g.y, gg2 = g.z * g.z, gg3 = g.w * g.w;
            P0[0] += ab.z * gg0;  P0[1] += ab.z * gg1;  P0[2] += ab.z * gg2;  P0[3] += ab.z * gg3;
            P1[0] += ab.w * gg0;  P1[1] += ab.w * gg1;  P1[2] += ab.w * gg2;  P1[3] += ab.w * gg3;
        }
    }
    {
        float4* sp = (float4*)(sP + (ms * 32 + ts) * 16);
        sp[0] = make_float4(M0[0], M0[1], M0[2], M0[3]);
        sp[1] = make_float4(M1[0], M1[1], M1[2], M1[3]);
        sp[2] = make_float4(P0[0], P0[1], P0[2], P0[3]);
        sp[3] = make_float4(P1[0], P1[1], P1[2], P1[3]);
    }
    __syncthreads();

    // ---- phase 2: combine ms partials + contraction (threads 0-127) ----
    if (tid < 128) {
        int tts = tid >> 2, c = tid & 3;
        float m0 = 0.f, m1 = 0.f, q0 = 0.f, q1 = 0.f;
#pragma unroll
        for (int w = 0; w < 8; w++) {
            const float* sp = sP + (w * 32 + tts) * 16;
            m0 += sp[c];
            m1 += sp[4 + c];
            q0 += sp[8 + c];
            q1 += sp[12 + c];
        }
        int gt = hf * 128 + tid;   // global t
        float4 ab = sAB[gt];
        float pv[8];
        pv[0] = ab.x * m0;      pv[1] = ab.z * m0 * m0;
        pv[2] = ab.z * q0;      pv[3] = sU0[gt] * m0;
        pv[4] = ab.y * m1;      pv[5] = ab.w * m1 * m1;
        pv[6] = ab.w * q1;      pv[7] = sU1[gt] * m1;
#pragma unroll
        for (int k = 0; k < 8; k++) {
            float v = pv[k];
#pragma unroll
            for (int o = 16; o > 0; o >>= 1) v += __shfl_down_sync(0xFFFFFFFFu, v, o);
            pv[k] = v;
        }
        if (lane == 0) {
#pragma unroll
            for (int k = 0; k < 8; k++) sred[wid][k] = pv[k];
        }
    }
    __syncthreads();
    if (tid < 8) {
        float t = sred[0][tid] + sred[1][tid] + sred[2][tid] + sred[3][tid];
        atomicAdd(&g_QRZU[p][tid], t);
    }

    // ---- global ticket: one block runs the nonlinear tail ----
    __threadfence();
    __shared__ unsigned int slast;
    if (tid == 0) slast = (atomicAdd(&g_done, 1u) == NBM - 1) ? 1u : 0u;
    __syncthreads();
    if (slast) {
        __threadfence();
        int n = tid;
        int pp = n >> 1, sel = n & 1;
        float Q = g_QRZU[pp][4 * sel + 0];
        float R = g_QRZU[pp][4 * sel + 1];
        float Z = g_QRZU[pp][4 * sel + 2];
        float U = g_QRZU[pp][4 * sel + 3];
        float a = g_aLY[pp][3 * sel + 0] + b2[n];
        float L = g_aLY[pp][3 * sel + 1];
        float Y = g_aLY[pp][3 * sel + 2];
        float g = tanhf(a), gw = 1.f - g * g;
        float g1 = gw;
        float g2 = -2.f * g * gw;
        float g3 = (4.f * g * g - 2.f * gw) * gw;
        float g4 = (16.f * gw - 8.f * g * g) * g * gw;
        float val = g4 * Q * Q
                  + g3 * (2.f * L * Q + 4.f * R)
                  + g2 * (L * L + 2.f * Z + 4.f * U)
                  + g1 * Y;
        double d = (double)(__ldg(&W3[n]) * val);
#pragma unroll
        for (int o = 16; o > 0; o >>= 1) d += __shfl_down_sync(0xFFFFFFFFu, d, o);
        if (lane == 0) sdr[wid] = d;
        __syncthreads();
        if (wid == 0) {
            double v = (lane < 8) ? sdr[lane] : 0.0;
#pragma unroll
            for (int o = 4; o > 0; o >>= 1) v += __shfl_down_sync(0xFFu, v, o);
            if (lane == 0) {
                out[0] = (float)v;
                g_done = 0u;       // reset for next graph replay
                __threadfence();
            }
        }
    }
}

// ---------------- launch ----------------
extern "C" void kernel_launch(void* const* d_in, const int* in_sizes, int n_in,
                              void* d_out, int out_size) {
    const float* x  = (const float*)d_in[0];
    const float* W1 = (const float*)d_in[1];
    const float* b1 = (const float*)d_in[2];
    const float* W2 = (const float*)d_in[3];
    const float* b2 = (const float*)d_in[4];
    const float* W3 = (const float*)d_in[5];
    // d_in[6] = b3: does not affect the 4th derivative
    float* out = (float*)d_out;

    k_pre<<<129, 256>>>(x, W1, b1);
    k_main<<<NBM, 256>>>(W2, W3, b2, out);
}

// round 15
// speedup vs baseline: 1.9529x; 1.1456x over previous
#include <cuda_runtime.h>
#include <cstdint>

#define H 256
#define DD 64
#define NPAIR 128
#define NBM (2 * NPAIR)     // k_main blocks: (pair, t-half)

// ---------------- persistent device state (no allocations) ----------------
__device__ __align__(16) float g_G[H * H];          // Gram (symmetric)
__device__ __align__(16) float g_h[H], g_h1[H], g_h2[H], g_u3[H], g_h2s[H], g_h4s2[H];
__device__ __align__(16) float g_QRZU[NPAIR][8];    // zeroed by k_pre each replay
__device__ __align__(16) float g_aLY[NPAIR][6];     // {a0,L0,Y0,a1,L1,Y1}
__device__ unsigned int g_done = 0;

// ---------------- kernel 1: uniform Gram + fused per-row chain (128 blocks) ----
__global__ __launch_bounds__(256) void k_pre(
    const float* __restrict__ x,  const float* __restrict__ W1,
    const float* __restrict__ b1)
{
    __shared__ float srow[2][DD];
    __shared__ float sx[DD];
    int tid = threadIdx.x;
    int wid = tid >> 5, lane = tid & 31;
    int m0 = 2 * blockIdx.x;

    if (tid < 2 * DD) srow[tid >> 6][tid & 63] = W1[(m0 + (tid >> 6)) * DD + (tid & 63)];
    else if (tid < 2 * DD + DD) sx[tid - 2 * DD] = x[tid - 2 * DD];
    if (tid >= 192 && tid < 200) g_QRZU[blockIdx.x][tid - 192] = 0.f;
    __syncthreads();

    // Gram rows m0, m0+1 (all 256 threads; t = tid)
    const float4* myr = (const float4*)(W1 + tid * DD);
    float a0 = 0.f, a1 = 0.f;
#pragma unroll
    for (int i = 0; i < DD / 4; i++) {
        float4 v = __ldg(myr + i);
        a0 += srow[0][4*i]*v.x + srow[0][4*i+1]*v.y + srow[0][4*i+2]*v.z + srow[0][4*i+3]*v.w;
        a1 += srow[1][4*i]*v.x + srow[1][4*i+1]*v.y + srow[1][4*i+2]*v.z + srow[1][4*i+3]*v.w;
    }
    g_G[(m0 + 0) * H + tid] = a0;
    g_G[(m0 + 1) * H + tid] = a1;

    // chain for this block's two rows (warps 0 and 1, from smem)
    if (wid < 2) {
        float v0 = srow[wid][lane], v1 = srow[wid][lane + 32];
        float z = v0 * sx[lane] + v1 * sx[lane + 32];
        float s = v0 * v0 + v1 * v1;
#pragma unroll
        for (int o = 16; o > 0; o >>= 1) {
            z += __shfl_down_sync(0xFFFFFFFFu, z, o);
            s += __shfl_down_sync(0xFFFFFFFFu, s, o);
        }
        if (lane == 0) {
            int m = m0 + wid;
            z += b1[m];
            float h = tanhf(z), w = 1.f - h * h;
            float h2 = -2.f * h * w;
            float h3 = (4.f * h * h - 2.f * w) * w;
            float h4 = (16.f * w - 8.f * h * h) * h * w;
            g_h[m]    = h;
            g_h1[m]   = w;
            g_h2[m]   = h2;
            g_u3[m]   = h3 * s;
            g_h2s[m]  = h2 * s;
            g_h4s2[m] = h4 * s * s;
        }
    }
}

// ---------------- kernel 2: streaming contraction, grid = (pair, t-half) ----------------
__global__ __launch_bounds__(256, 2) void k_main(
    const float* __restrict__ W2, const float* __restrict__ W3,
    const float* __restrict__ b2, float* __restrict__ out)
{
    __shared__ float  sP[8 * 32 * 16];   // phase-1 partials [ms][ts][16] = 16KB
    __shared__ float4 sAB[H];            // {A0, A1, B0, B1} (4KB)
    __shared__ float  sU0[H], sU1[H];    // 2KB
    __shared__ float  sred[4][8];
    __shared__ float  sredA[8][6];
    __shared__ double sdr[8];

    int tid = threadIdx.x;
    int bx = blockIdx.x;
    int p = bx >> 1, hf = bx & 1;
    int wid = tid >> 5, lane = tid & 31;
    int n0 = 2 * p;

    // ---- setup: coefficient vectors + full-m a/L/Y partials ----
    float aa0, aa1, LL0, LL1, YY0, YY1;
    {
        int m = tid;
        float h1 = g_h1[m], h2 = g_h2[m], u3 = g_u3[m];
        float hh = g_h[m], h2s = g_h2s[m], h4s2 = g_h4s2[m];
        float w20 = __ldg(&W2[n0 * H + m]);
        float w21 = __ldg(&W2[(n0 + 1) * H + m]);
        sAB[m] = make_float4(w20 * h1, w21 * h1, w20 * h2, w21 * h2);
        sU0[m] = w20 * u3;
        sU1[m] = w21 * u3;
        aa0 = w20 * hh;   aa1 = w21 * hh;
        LL0 = w20 * h2s;  LL1 = w21 * h2s;
        YY0 = w20 * h4s2; YY1 = w21 * h4s2;
    }
    // hf=0 publishes full a/L/Y for this pair (block reduce over all 256 m)
    if (hf == 0) {
        float v[6] = {aa0, LL0, YY0, aa1, LL1, YY1};
#pragma unroll
        for (int k = 0; k < 6; k++) {
            float t = v[k];
#pragma unroll
            for (int o = 16; o > 0; o >>= 1) t += __shfl_down_sync(0xFFFFFFFFu, t, o);
            v[k] = t;
        }
        if (lane == 0) {
#pragma unroll
            for (int k = 0; k < 6; k++) sredA[wid][k] = v[k];
        }
    }
    __syncthreads();
    if (hf == 0 && tid < 6) {
        float t = 0.f;
#pragma unroll
        for (int w = 0; w < 8; w++) t += sredA[w][tid];
        g_aLY[p][tid] = t;
    }

    // ---- phase 1: pipelined G stream; thread = (ms = tid>>5, ts = tid&31) ----
    int ms = tid >> 5, ts = tid & 31;
    float M0[4] = {0,0,0,0}, M1[4] = {0,0,0,0};
    float P0[4] = {0,0,0,0}, P1[4] = {0,0,0,0};

    const float4* Gp = (const float4*)g_G + (32 * ms) * (H / 4) + hf * 32 + ts;
    const float4* abp = sAB + 32 * ms;

    float4 buf[2][8];
#pragma unroll
    for (int u = 0; u < 8; u++) buf[0][u] = __ldg(Gp + u * (H / 4));

#pragma unroll
    for (int bb = 0; bb < 4; bb++) {
        int cur = bb & 1, nxt = cur ^ 1;
        if (bb < 3) {
#pragma unroll
            for (int u = 0; u < 8; u++)
                buf[nxt][u] = __ldg(Gp + (8 * (bb + 1) + u) * (H / 4));
        }
#pragma unroll
        for (int u = 0; u < 8; u++) {
            float4 ab = abp[8 * bb + u];
            float4 g = buf[cur][u];
            M0[0] += ab.x * g.x;  M0[1] += ab.x * g.y;  M0[2] += ab.x * g.z;  M0[3] += ab.x * g.w;
            M1[0] += ab.y * g.x;  M1[1] += ab.y * g.y;  M1[2] += ab.y * g.z;  M1[3] += ab.y * g.w;
            float gg0 = g.x * g.x, gg1 = g.y * g.y, gg2 = g.z * g.z, gg3 = g.w * g.w;
            P0[0] += ab.z * gg0;  P0[1] += ab.z * gg1;  P0[2] += ab.z * gg2;  P0[3] += ab.z * gg3;
            P1[0] += ab.w * gg0;  P1[1] += ab.w * gg1;  P1[2] += ab.w * gg2;  P1[3] += ab.w * gg3;
        }
    }
    {
        float4* sp = (float4*)(sP + (ms * 32 + ts) * 16);
        sp[0] = make_float4(M0[0], M0[1], M0[2], M0[3]);
        sp[1] = make_float4(M1[0], M1[1], M1[2], M1[3]);
        sp[2] = make_float4(P0[0], P0[1], P0[2], P0[3]);
        sp[3] = make_float4(P1[0], P1[1], P1[2], P1[3]);
    }
    __syncthreads();

    // ---- phase 2: combine ms partials + contraction (threads 0-127) ----
    if (tid < 128) {
        int tts = tid >> 2, c = tid & 3;
        float m0 = 0.f, m1 = 0.f, q0 = 0.f, q1 = 0.f;
#pragma unroll
        for (int w = 0; w < 8; w++) {
            const float* sp = sP + (w * 32 + tts) * 16;
            m0 += sp[c];
            m1 += sp[4 + c];
            q0 += sp[8 + c];
            q1 += sp[12 + c];
        }
        int gt = hf * 128 + tid;   // global t
        float4 ab = sAB[gt];
        float pv[8];
        pv[0] = ab.x * m0;      pv[1] = ab.z * m0 * m0;
        pv[2] = ab.z * q0;      pv[3] = sU0[gt] * m0;
        pv[4] = ab.y * m1;      pv[5] = ab.w * m1 * m1;
        pv[6] = ab.w * q1;      pv[7] = sU1[gt] * m1;
#pragma unroll
        for (int k = 0; k < 8; k++) {
            float v = pv[k];
#pragma unroll
            for (int o = 16; o > 0; o >>= 1) v += __shfl_down_sync(0xFFFFFFFFu, v, o);
            pv[k] = v;
        }
        if (lane == 0) {
#pragma unroll
            for (int k = 0; k < 8; k++) sred[wid][k] = pv[k];
        }
    }
    __syncthreads();
    if (tid < 8) {
        float t = sred[0][tid] + sred[1][tid] + sred[2][tid] + sred[3][tid];
        atomicAdd(&g_QRZU[p][tid], t);
    }

    // ---- global ticket: one block runs the nonlinear tail ----
    __threadfence();
    __shared__ unsigned int slast;
    if (tid == 0) slast = (atomicAdd(&g_done, 1u) == NBM - 1) ? 1u : 0u;
    __syncthreads();
    if (slast) {
        __threadfence();
        int n = tid;
        int pp = n >> 1, sel = n & 1;
        float Q = g_QRZU[pp][4 * sel + 0];
        float R = g_QRZU[pp][4 * sel + 1];
        float Z = g_QRZU[pp][4 * sel + 2];
        float U = g_QRZU[pp][4 * sel + 3];
        float a = g_aLY[pp][3 * sel + 0] + b2[n];
        float L = g_aLY[pp][3 * sel + 1];
        float Y = g_aLY[pp][3 * sel + 2];
        float g = tanhf(a), gw = 1.f - g * g;
        float g1 = gw;
        float g2 = -2.f * g * gw;
        float g3 = (4.f * g * g - 2.f * gw) * gw;
        float g4 = (16.f * gw - 8.f * g * g) * g * gw;
        float val = g4 * Q * Q
                  + g3 * (2.f * L * Q + 4.f * R)
                  + g2 * (L * L + 2.f * Z + 4.f * U)
                  + g1 * Y;
        double d = (double)(__ldg(&W3[n]) * val);
#pragma unroll
        for (int o = 16; o > 0; o >>= 1) d += __shfl_down_sync(0xFFFFFFFFu, d, o);
        if (lane == 0) sdr[wid] = d;
        __syncthreads();
        if (wid == 0) {
            double v = (lane < 8) ? sdr[lane] : 0.0;
#pragma unroll
            for (int o = 4; o > 0; o >>= 1) v += __shfl_down_sync(0xFFu, v, o);
            if (lane == 0) {
                out[0] = (float)v;
                g_done = 0u;       // reset for next graph replay
                __threadfence();
            }
        }
    }
}

// ---------------- launch ----------------
extern "C" void kernel_launch(void* const* d_in, const int* in_sizes, int n_in,
                              void* d_out, int out_size) {
    const float* x  = (const float*)d_in[0];
    const float* W1 = (const float*)d_in[1];
    const float* b1 = (const float*)d_in[2];
    const float* W2 = (const float*)d_in[3];
    const float* b2 = (const float*)d_in[4];
    const float* W3 = (const float*)d_in[5];
    // d_in[6] = b3: does not affect the 4th derivative
    float* out = (float*)d_out;

    k_pre<<<NPAIR, 256>>>(x, W1, b1);
    k_main<<<NBM, 256>>>(W2, W3, b2, out);
}